// round 10
// baseline (speedup 1.0000x reference)
#include <cuda_runtime.h>
#include <cstddef>

// GloVe loss — exact counting-sort by center, two-level with FINE buckets
// (c>>5: 3125 buckets of ~84 records) for parallel cheap in-bucket sort,
// + byte-bound main gather with register-held center-row reuse (16-rec runs).
// Launches: hist -> scan -> scatter -> sort2 -> main.

static constexpr int EMB           = 300;
static constexpr int NV4           = EMB / 4;       // 75 float4 per row
static constexpr int BATCH_N       = 262144;

static constexpr int BUCKET_SHIFT  = 5;
static constexpr int NB            = 4096;          // covers 100000>>5 = 3125
static constexpr int NB_USED       = 3125;
static constexpr int SORT_CAP      = 256;           // avg bucket 84, sd ~9

static constexpr int STHREADS      = 512;
static constexpr int SCHUNK        = 2048;
static constexpr int SBLOCKS      = BATCH_N / SCHUNK;   // 128
static constexpr int SPT           = SCHUNK / STHREADS;  // 4

static constexpr int THREADS       = 256;
static constexpr int WARPS_PER_BLK = THREADS / 32;  // 8
static constexpr int ROWS_PER_WARP = 16;
static constexpr int MBLOCKS       = BATCH_N / (WARPS_PER_BLK * ROWS_PER_WARP); // 2048

// Replay-safe: g_cnt zeroed by scan after read; g_base fully rewritten;
// s_recs fully overwritten; g_acc/g_done reset by last main block.
__device__ int    g_cnt[NB];
__device__ int    g_base[NB];
__device__ int4   s_recs[BATCH_N];
__device__ double g_acc;
__device__ unsigned int g_done;

// ---- 1) histogram by c>>5 (smem-aggregated) ---------------------------------
__global__ __launch_bounds__(STHREADS) void glove_hist_kernel(
    const int* __restrict__ center)
{
    __shared__ int h[NB];
    const int tid  = threadIdx.x;
    const int idx0 = blockIdx.x * SCHUNK;
    for (int i = tid; i < NB; i += STHREADS) h[i] = 0;
    __syncthreads();
    #pragma unroll
    for (int k = 0; k < SPT; ++k) {
        const int c = __ldg(center + idx0 + k * STHREADS + tid);
        atomicAdd(&h[c >> BUCKET_SHIFT], 1);
    }
    __syncthreads();
    for (int b = tid; b < NB; b += STHREADS)
        if (h[b]) atomicAdd(&g_cnt[b], h[b]);
}

// ---- 2) exclusive scan over 4096 (1 block, 4 elems/thread); re-zero counts --
__global__ __launch_bounds__(1024) void glove_scan_kernel()
{
    __shared__ int tmp[1024];
    const int t = threadIdx.x;
    int v[4], s = 0;
    #pragma unroll
    for (int k = 0; k < 4; ++k) {
        v[k] = g_cnt[t * 4 + k];
        g_cnt[t * 4 + k] = 0;           // restore for next replay
        s += v[k];
    }
    tmp[t] = s;
    __syncthreads();
    #pragma unroll
    for (int off = 1; off < 1024; off <<= 1) {
        int u = (t >= off) ? tmp[t - off] : 0;
        __syncthreads();
        tmp[t] += u;
        __syncthreads();
    }
    int run = tmp[t] - s;               // exclusive prefix of this thread's 4
    #pragma unroll
    for (int k = 0; k < 4; ++k) {
        g_base[t * 4 + k] = run;
        run += v[k];
    }
}

// ---- 3) bucketed scatter ----------------------------------------------------
// After this kernel, g_base[b] == END offset of bucket b.
__global__ __launch_bounds__(STHREADS) void glove_scatter_kernel(
    const int*   __restrict__ center,
    const int*   __restrict__ outside,
    const float* __restrict__ coocs,
    const float* __restrict__ weighting)
{
    __shared__ int h[NB];
    __shared__ int base[NB];
    const int tid  = threadIdx.x;
    const int idx0 = blockIdx.x * SCHUNK;

    for (int i = tid; i < NB; i += STHREADS) h[i] = 0;
    __syncthreads();

    int c[SPT];
    #pragma unroll
    for (int k = 0; k < SPT; ++k) {
        c[k] = __ldg(center + idx0 + k * STHREADS + tid);
        atomicAdd(&h[c[k] >> BUCKET_SHIFT], 1);
    }
    __syncthreads();
    for (int b = tid; b < NB; b += STHREADS) {
        const int n = h[b];
        base[b] = n ? atomicAdd(&g_base[b], n) : 0;
    }
    __syncthreads();
    for (int i = tid; i < NB; i += STHREADS) h[i] = 0;   // reuse as cursors
    __syncthreads();

    #pragma unroll
    for (int k = 0; k < SPT; ++k) {
        const int i = idx0 + k * STHREADS + tid;
        const int b = c[k] >> BUCKET_SHIFT;
        const int off = atomicAdd(&h[b], 1);
        int4 rec;
        rec.x = c[k];
        rec.y = __ldg(outside + i);
        rec.z = __float_as_int(__ldg(coocs + i));
        rec.w = __float_as_int(__ldg(weighting + i));
        s_recs[base[b] + off] = rec;
    }
}

// ---- 3b) in-bucket counting sort by c&31 (light blocks, 3125-way parallel) --
__global__ __launch_bounds__(128) void glove_sort2_kernel()
{
    __shared__ int4 buf[SORT_CAP];
    __shared__ int  cnt[32];
    __shared__ int  pos[32];
    const int b   = blockIdx.x;
    const int tid = threadIdx.x;
    const int s   = (b == 0) ? 0 : g_base[b - 1];
    const int n   = g_base[b] - s;
    if (n <= 0 || n > SORT_CAP) return;  // >CAP ~never; perf-only fallback

    if (tid < 32) cnt[tid] = 0;
    __syncthreads();
    for (int i = tid; i < n; i += 128) {
        const int4 r = __ldg(&s_recs[s + i]);
        buf[i] = r;
        atomicAdd(&cnt[r.x & 31], 1);
    }
    __syncthreads();
    if (tid < 32) {                      // warp-level exclusive scan of 32
        int x = cnt[tid];
        int incl = x;
        #pragma unroll
        for (int off = 1; off < 32; off <<= 1) {
            int u = __shfl_up_sync(0xffffffffu, incl, off);
            if (tid >= off) incl += u;
        }
        pos[tid] = incl - x;
    }
    __syncthreads();
    for (int i = tid; i < n; i += 128) {
        const int4 r = buf[i];
        s_recs[s + atomicAdd(&pos[r.x & 31], 1)] = r;
    }
}

// ---- 4) main gather with center-row register reuse --------------------------
__global__ __launch_bounds__(THREADS, 6) void glove_main_kernel(
    const float* __restrict__ cemb,
    const float* __restrict__ oemb,
    const float* __restrict__ cbias,
    const float* __restrict__ obias,
    float*       __restrict__ out)
{
    const int lane  = threadIdx.x & 31;
    const int warp  = threadIdx.x >> 5;
    const int gwarp = blockIdx.x * WARPS_PER_BLK + warp;

    const float4* __restrict__ cemb4 = reinterpret_cast<const float4*>(cemb);
    const float4* __restrict__ oemb4 = reinterpret_cast<const float4*>(oemb);

    float wsum = 0.0f;
    int   prev = -1;
    float4 a0, a1, a2;
    float  cb = 0.0f;
    a0 = a1 = a2 = make_float4(0.f, 0.f, 0.f, 0.f);

    #pragma unroll 1
    for (int r = 0; r < ROWS_PER_WARP; ++r) {
        const int row = gwarp * ROWS_PER_WARP + r;
        const int4 rec = __ldg(&s_recs[row]);

        const unsigned oo = (unsigned)rec.y * (unsigned)NV4 + (unsigned)lane;
        float4 b0 = __ldg(oemb4 + oo);
        float4 b1 = __ldg(oemb4 + oo + 32);
        float4 b2 = make_float4(0.f, 0.f, 0.f, 0.f);
        if (lane < NV4 - 64) b2 = __ldg(oemb4 + oo + 64);
        const float obv = __ldg(obias + rec.y);

        if (rec.x != prev) {   // warp-uniform branch (records sorted by center)
            const unsigned co = (unsigned)rec.x * (unsigned)NV4 + (unsigned)lane;
            a0 = __ldg(cemb4 + co);
            a1 = __ldg(cemb4 + co + 32);
            a2 = make_float4(0.f, 0.f, 0.f, 0.f);
            if (lane < NV4 - 64) a2 = __ldg(cemb4 + co + 64);
            cb = __ldg(cbias + rec.x);
            prev = rec.x;
        }

        float dot = a0.x * b0.x + a0.y * b0.y + a0.z * b0.z + a0.w * b0.w;
        dot      += a1.x * b1.x + a1.y * b1.y + a1.z * b1.z + a1.w * b1.w;
        dot      += a2.x * b2.x + a2.y * b2.y + a2.z * b2.z + a2.w * b2.w;

        #pragma unroll
        for (int off = 16; off; off >>= 1)
            dot += __shfl_xor_sync(0xffffffffu, dot, off);

        if (lane == 0) {
            const float err = dot + cb + obv - __int_as_float(rec.z);
            wsum += __int_as_float(rec.w) * err * err;
        }
    }

    __shared__ float sh[WARPS_PER_BLK];
    if (lane == 0) sh[warp] = wsum;
    __syncthreads();

    if (threadIdx.x == 0) {
        float s = 0.0f;
        #pragma unroll
        for (int i = 0; i < WARPS_PER_BLK; ++i) s += sh[i];
        atomicAdd(&g_acc, (double)s);

        __threadfence();
        const unsigned t = atomicAdd(&g_done, 1u);
        if (t == (unsigned)(MBLOCKS - 1)) {
            const double v = atomicAdd(&g_acc, 0.0);
            out[0] = (float)v;
            g_acc  = 0.0;
            g_done = 0u;
        }
    }
}

extern "C" void kernel_launch(void* const* d_in, const int* in_sizes, int n_in,
                              void* d_out, int out_size) {
    const int*   center    = (const int*)  d_in[0];
    const int*   outside   = (const int*)  d_in[1];
    const float* coocs     = (const float*)d_in[2];
    const float* weighting = (const float*)d_in[3];
    const float* cemb      = (const float*)d_in[4];
    const float* oemb      = (const float*)d_in[5];
    const float* cbias     = (const float*)d_in[6];
    const float* obias     = (const float*)d_in[7];
    float* out = (float*)d_out;

    glove_hist_kernel<<<SBLOCKS, STHREADS>>>(center);
    glove_scan_kernel<<<1, 1024>>>();
    glove_scatter_kernel<<<SBLOCKS, STHREADS>>>(center, outside, coocs, weighting);
    glove_sort2_kernel<<<NB_USED, 128>>>();
    glove_main_kernel<<<MBLOCKS, THREADS>>>(cemb, oemb, cbias, obias, out);
}